// round 15
// baseline (speedup 1.0000x reference)
#include <cuda_runtime.h>
#include <cuda_bf16.h>
#include <cstdint>

// Fixed shapes: B=4, S=1024, E=1024, width=768 -> H=12, D=64
#define Bq   4
#define Sq   1024
#define Eq   1024
#define Wd   768
#define Hh   12
#define Dd   64
#define BSq  (Bq*Sq)
#define NZ   (Bq*Hh)
#define WW   (Wd*Wd)
#define OUT_ELEMS   ((long long)BSq*Wd)
#define ATTN_ELEMS  ((long long)NZ*Sq*Sq)

// ---------------- scratch (device globals; no runtime allocation) ----------
__device__ __align__(16) ushort g_xh[BSq*Wd], g_xl[BSq*Wd];
__device__ __align__(16) ushort g_wh[4*WW],  g_wl[4*WW];
__device__ __align__(16) ushort g_qh[BSq*Wd], g_ql[BSq*Wd];
__device__ __align__(16) ushort g_kh[BSq*Wd], g_kl[BSq*Wd];
__device__ __align__(16) ushort g_vh[BSq*Wd], g_vl[BSq*Wd];
__device__ __align__(16) ushort g_ch[BSq*Wd], g_cl[BSq*Wd];
__device__ __align__(16) float g_attn_fallback[NZ*Sq*Sq];

// ======================= primitives ========================================
__device__ __forceinline__ void ldsm_x4(uint32_t* r, uint32_t addr) {
    asm volatile("ldmatrix.sync.aligned.m8n8.x4.shared.b16 {%0,%1,%2,%3}, [%4];"
        : "=r"(r[0]), "=r"(r[1]), "=r"(r[2]), "=r"(r[3]) : "r"(addr));
}
__device__ __forceinline__ void ldsm_x4_t(uint32_t* r, uint32_t addr) {
    asm volatile("ldmatrix.sync.aligned.m8n8.x4.trans.shared.b16 {%0,%1,%2,%3}, [%4];"
        : "=r"(r[0]), "=r"(r[1]), "=r"(r[2]), "=r"(r[3]) : "r"(addr));
}
__device__ __forceinline__ void mma_bf16(float* c, const uint32_t* a,
                                         uint32_t b0, uint32_t b1) {
    asm volatile("mma.sync.aligned.m16n8k16.row.col.f32.bf16.bf16.f32 "
        "{%0,%1,%2,%3}, {%4,%5,%6,%7}, {%8,%9}, {%0,%1,%2,%3};"
        : "+f"(c[0]), "+f"(c[1]), "+f"(c[2]), "+f"(c[3])
        : "r"(a[0]), "r"(a[1]), "r"(a[2]), "r"(a[3]), "r"(b0), "r"(b1));
}
__device__ __forceinline__ void split_bf(float v, ushort& h, ushort& l) {
    __nv_bfloat16 hh = __float2bfloat16(v);
    h = __bfloat16_as_ushort(hh);
    l = __bfloat16_as_ushort(__float2bfloat16(v - __bfloat162float(hh)));
}
__device__ __forceinline__ void cp16(uint32_t dst, const void* src) {
    asm volatile("cp.async.cg.shared.global [%0], [%1], 16;" :: "r"(dst), "l"(src));
}
#define CP_COMMIT() asm volatile("cp.async.commit_group;" ::: "memory")
#define CP_WAIT(n)  asm volatile("cp.async.wait_group %0;" :: "n"(n) : "memory")

// ===========================================================================
// conv_kernel: fp32 (stride 1024) -> bf16 hi/lo (stride 768), once.
// ===========================================================================
__global__ __launch_bounds__(256)
void conv_kernel(const float* __restrict__ x,
                 const float* __restrict__ qw, const float* __restrict__ kw,
                 const float* __restrict__ vw, const float* __restrict__ ow) {
    const int z = blockIdx.y;
    const float* src; ushort* dh; ushort* dl; int rows;
    if (z == 0)      { src = x;  dh = g_xh;        dl = g_xl;        rows = BSq; }
    else if (z == 1) { src = qw; dh = g_wh;        dl = g_wl;        rows = Wd; }
    else if (z == 2) { src = kw; dh = g_wh + WW;   dl = g_wl + WW;   rows = Wd; }
    else if (z == 3) { src = vw; dh = g_wh + 2*WW; dl = g_wl + 2*WW; rows = Wd; }
    else             { src = ow; dh = g_wh + 3*WW; dl = g_wl + 3*WW; rows = Wd; }

    const int idx = blockIdx.x * 256 + threadIdx.x;
    const int total = rows * (Wd / 2);
    if (idx >= total) return;
    const int row = idx / (Wd / 2);
    const int c2 = (idx - row * (Wd / 2)) * 2;
    float2 v = *(const float2*)(src + (size_t)row * Eq + c2);
    ushort h0, l0, h1, l1;
    split_bf(v.x, h0, l0);
    split_bf(v.y, h1, l1);
    *(ushort2*)(dh + (size_t)row * Wd + c2) = make_ushort2(h0, h1);
    *(ushort2*)(dl + (size_t)row * Wd + c2) = make_ushort2(l0, l1);
}

// ===========================================================================
// proj_mma: bf16x3 HMMA GEMM, cp.async double-buffered, K-chunk 32. (R12)
// ===========================================================================
#define PP 40                          // smem pitch in ushorts (80B)
#define PROJ_TILE (128*PP)             // 5120 ushorts per array
#define PROJ_BUF  (4*PROJ_TILE)        // Ah|Al|Bh|Bl = 20480 ushorts
#define PROJ_SMEM (2*PROJ_BUF*2)       // 81920 bytes

__global__ __launch_bounds__(256, 2)
void proj_mma(int mode, const float* __restrict__ b0, const float* __restrict__ b1,
              const float* __restrict__ b2, float* __restrict__ out_ext) {
    extern __shared__ ushort psm[];

    const int t = threadIdx.x;
    const int wid = t >> 5;
    const int lane = t & 31;

    const ushort *Axh, *Axl, *Wxh, *Wxl;
    const float* bias;
    ushort *oh = nullptr, *ol = nullptr;
    if (mode == 1) {
        Axh = g_ch; Axl = g_cl;
        Wxh = g_wh + 3*WW; Wxl = g_wl + 3*WW;
        bias = b0;
    } else {
        Axh = g_xh; Axl = g_xl;
        const int z = blockIdx.z;
        Wxh = g_wh + z*WW; Wxl = g_wl + z*WW;
        bias = (z == 0) ? b0 : (z == 1) ? b1 : b2;
        if (z == 0)      { oh = g_qh; ol = g_ql; }
        else if (z == 1) { oh = g_kh; ol = g_kl; }
        else             { oh = g_vh; ol = g_vl; }
    }

    const int n0 = blockIdx.x * 128;
    const int i0 = blockIdx.y * 128;
    const int wm = (wid & 3) * 32;
    const int wn = (wid >> 2) * 64;

    const uint32_t sb = (uint32_t)__cvta_generic_to_shared(psm);

    const ushort* s4[4] = { Axh + (size_t)i0 * Wd,
                            Axl + (size_t)i0 * Wd,
                            Wxh + (size_t)n0 * Wd,
                            Wxl + (size_t)n0 * Wd };

    auto prefetch = [&](int c, int bsel) {
        const int k0 = c * 32;
        const uint32_t base = sb + bsel * (PROJ_BUF * 2);
        #pragma unroll
        for (int u = 0; u < 8; u++) {
            const int arr = u >> 1;
            const int id = ((u & 1) << 8) + t;
            const int row = id >> 2, ch = id & 3;
            cp16(base + (arr * PROJ_TILE + row * PP + ch * 8) * 2,
                 s4[arr] + (size_t)row * Wd + k0 + ch * 8);
        }
        CP_COMMIT();
    };

    float acc[2][8][4];
    #pragma unroll
    for (int mi = 0; mi < 2; mi++)
        #pragma unroll
        for (int ni = 0; ni < 8; ni++)
            #pragma unroll
            for (int j = 0; j < 4; j++) acc[mi][ni][j] = 0.f;

    const int frag_row = ((lane >> 3) & 1) * 8 + (lane & 7);
    const int frag_koff = (lane >> 4) * 16;
    const int bfrag_row = ((lane >> 4) & 1) * 8 + (lane & 7);
    const int bfrag_koff = ((lane >> 3) & 1) * 16;

    prefetch(0, 0);

    for (int c = 0; c < 24; c++) {
        if (c + 1 < 24) { prefetch(c + 1, (c + 1) & 1); CP_WAIT(1); }
        else            { CP_WAIT(0); }
        __syncthreads();

        const uint32_t bb = sb + (c & 1) * (PROJ_BUF * 2);
        const uint32_t a_base  = bb;
        const uint32_t al_base = bb + PROJ_TILE * 2;
        const uint32_t b_base  = bb + 2 * PROJ_TILE * 2;
        const uint32_t bl_base = bb + 3 * PROJ_TILE * 2;

        #pragma unroll
        for (int kb = 0; kb < 2; kb++) {
            uint32_t ah[2][4], alr[2][4];
            #pragma unroll
            for (int mi = 0; mi < 2; mi++) {
                const uint32_t off = (uint32_t)((wm + mi * 16 + frag_row) * (PP*2)
                                                + kb * 32 + frag_koff);
                ldsm_x4(ah[mi], a_base + off);
                ldsm_x4(alr[mi], al_base + off);
            }
            #pragma unroll
            for (int g = 0; g < 4; g++) {
                uint32_t bh[4], blr[4];
                const uint32_t off = (uint32_t)((wn + g * 16 + bfrag_row) * (PP*2)
                                                + kb * 32 + bfrag_koff);
                ldsm_x4(bh, b_base + off);
                ldsm_x4(blr, bl_base + off);
                #pragma unroll
                for (int s = 0; s < 2; s++) {
                    #pragma unroll
                    for (int mi = 0; mi < 2; mi++) {
                        float* cc = acc[mi][g * 2 + s];
                        mma_bf16(cc, ah[mi],  bh[2*s],  bh[2*s+1]);
                        mma_bf16(cc, ah[mi],  blr[2*s], blr[2*s+1]);
                        mma_bf16(cc, alr[mi], bh[2*s],  bh[2*s+1]);
                    }
                }
            }
        }
        __syncthreads();
    }

    #pragma unroll
    for (int mi = 0; mi < 2; mi++) {
        #pragma unroll
        for (int ni = 0; ni < 8; ni++) {
            const int row = i0 + wm + mi * 16 + (lane >> 2);
            const int col = n0 + wn + ni * 8 + (lane & 3) * 2;
            float2 bb2 = *(const float2*)(bias + col);
            float v0 = acc[mi][ni][0] + bb2.x, v1 = acc[mi][ni][1] + bb2.y;
            float v2 = acc[mi][ni][2] + bb2.x, v3 = acc[mi][ni][3] + bb2.y;
            if (mode == 1) {
                *(float2*)(out_ext + (size_t)row * Wd + col) = make_float2(v0, v1);
                *(float2*)(out_ext + (size_t)(row + 8) * Wd + col) = make_float2(v2, v3);
            } else {
                ushort h0,l0,h1,l1,h2,l2,h3,l3;
                split_bf(v0,h0,l0); split_bf(v1,h1,l1);
                split_bf(v2,h2,l2); split_bf(v3,h3,l3);
                *(ushort2*)(oh + (size_t)row * Wd + col) = make_ushort2(h0,h1);
                *(ushort2*)(ol + (size_t)row * Wd + col) = make_ushort2(l0,l1);
                *(ushort2*)(oh + (size_t)(row + 8) * Wd + col) = make_ushort2(h2,h3);
                *(ushort2*)(ol + (size_t)(row + 8) * Wd + col) = make_ushort2(l2,l3);
            }
        }
    }
}

// ===========================================================================
// Attention smem geometry (pitch 72 ushorts = 144B)
// ===========================================================================
#define PITCH 72
#define QT    (128*PITCH)
#define KT    (64*PITCH)

__device__ __forceinline__ void prefetch_q(uint32_t sb, const ushort* qh,
                                           const ushort* ql, int t) {
    #pragma unroll
    for (int u = 0; u < 8; u++) {
        const int arr = u >> 2;
        const int rem = ((u & 3) << 8) + t;
        const int row = rem >> 3, ch = rem & 7;
        const ushort* src = (arr == 0 ? qh : ql) + (size_t)row * Wd + ch * 8;
        cp16(sb + (arr * QT + row * PITCH + ch * 8) * 2, src);
    }
    CP_COMMIT();
}

// ===========================================================================
// attn_mma: FUSED two-pass fixed-base-softmax flash attention.
// Pass A: PURE bf16 QK^T (hi only) -> row sums. Independent per-key exp
//   errors (~7e-4) average to ~3e-5 relative S error — safe vs 1e-3.
// Pass B: full bf16x3 QK^T, write P once, fused P@V (bf16x3).
// ===========================================================================
#define AV_KVB (4*KT)
#define AV_SMEM ((2*QT + 2*AV_KVB)*2 + Sq*4)
__global__ __launch_bounds__(256, 2)
void attn_mma(const int* __restrict__ mask, float* __restrict__ attn_out) {
    extern __shared__ ushort smem_u[];
    float* MA = (float*)(smem_u + 2*QT + 2*AV_KVB);

    float* attnW = attn_out ? attn_out : g_attn_fallback;

    const int t = threadIdx.x;
    const int wid = t >> 5;
    const int lane = t & 31;
    const int z = blockIdx.y;
    const int b = z / Hh;
    const int h = z - b * Hh;
    const int i0 = blockIdx.x * 128;
    const int wm = wid * 16;

    const size_t qoff = ((size_t)b * Sq + i0) * Wd + h * Dd;
    const size_t koff = (size_t)b * Sq * Wd + h * Dd;

    const uint32_t sb = (uint32_t)__cvta_generic_to_shared(smem_u);

    // Pass A: K-hi only (2 cp16/thread)
    auto prefetch_kh = [&](int jt, int bsel) {
        const uint32_t base = sb + (2*QT + bsel * AV_KVB) * 2;
        const size_t off = koff + (size_t)jt * 64 * Wd;
        #pragma unroll
        for (int u = 0; u < 2; u++) {
            const int rem = (u << 8) + t;
            const int row = rem >> 3, ch = rem & 7;
            cp16(base + (row * PITCH + ch * 8) * 2,
                 g_kh + off + (size_t)row * Wd + ch * 8);
        }
        CP_COMMIT();
    };
    auto prefetch_kv = [&](int jt, int bsel) {
        const uint32_t base = sb + (2*QT + bsel * AV_KVB) * 2;
        const size_t off = koff + (size_t)jt * 64 * Wd;
        const ushort* s4[4] = { g_kh + off, g_kl + off, g_vh + off, g_vl + off };
        #pragma unroll
        for (int u = 0; u < 8; u++) {
            const int arr = u >> 1;
            const int rem = ((u & 1) << 8) + t;
            const int row = rem >> 3, ch = rem & 7;
            cp16(base + (arr * KT + row * PITCH + ch * 8) * 2,
                 s4[arr] + (size_t)row * Wd + ch * 8);
        }
        CP_COMMIT();
    };

    prefetch_q(sb, g_qh + qoff, g_ql + qoff, t);
    prefetch_kh(0, 0);
    #pragma unroll
    for (int i = t; i < Sq; i += 256)
        MA[i] = __ldg(mask + b * Sq + i) ? 0.f : -1e9f;

    CP_WAIT(1);
    __syncthreads();

    const int frag_row = ((lane >> 3) & 1) * 8 + (lane & 7);
    const int frag_koff = (lane >> 4) * 16;
    const int bfrag_row = ((lane >> 4) & 1) * 8 + (lane & 7);
    const int bfrag_koff = ((lane >> 3) & 1) * 16;
    const int tfrag_row = ((lane >> 3) & 1) * 8 + (lane & 7);
    const int tfrag_noff = ((lane >> 4) & 1) * 16;

    uint32_t qh[4][4], ql[4][4];
    #pragma unroll
    for (int kb = 0; kb < 4; kb++) {
        const uint32_t off = (uint32_t)((wm + frag_row) * (PITCH * 2) + kb * 32 + frag_koff);
        ldsm_x4(qh[kb], sb + off);
        ldsm_x4(ql[kb], sb + QT * 2 + off);
    }

    // -------------------- Pass A: pure-bf16 row sums -------------------------
    float s0 = 0.f, s1 = 0.f;
    for (int jt = 0; jt < 16; jt++) {
        if (jt + 1 < 16) { prefetch_kh(jt + 1, (jt + 1) & 1); CP_WAIT(1); }
        else             { CP_WAIT(0); }
        __syncthreads();

        const uint32_t kh_base = sb + (2*QT + (jt & 1) * AV_KVB) * 2;
        const int j0 = jt * 64;

        #pragma unroll
        for (int p = 0; p < 4; p++) {
            float acc[2][4] = {};
            #pragma unroll
            for (int kb = 0; kb < 4; kb++) {
                uint32_t kh[4];
                const uint32_t off = (uint32_t)((p * 16 + bfrag_row) * (PITCH * 2) + kb * 32 + bfrag_koff);
                ldsm_x4(kh, kh_base + off);
                #pragma unroll
                for (int s = 0; s < 2; s++)
                    mma_bf16(acc[s], qh[kb], kh[2*s], kh[2*s+1]);
            }
            #pragma unroll
            for (int s = 0; s < 2; s++) {
                const int col = j0 + p * 16 + s * 8 + (lane & 3) * 2;
                const float ma0 = MA[col], ma1 = MA[col + 1];
                s0 += __expf(acc[s][0] * 0.125f + ma0) + __expf(acc[s][1] * 0.125f + ma1);
                s1 += __expf(acc[s][2] * 0.125f + ma0) + __expf(acc[s][3] * 0.125f + ma1);
            }
        }
        __syncthreads();
    }
    s0 += __shfl_xor_sync(0xffffffffu, s0, 1);
    s0 += __shfl_xor_sync(0xffffffffu, s0, 2);
    s1 += __shfl_xor_sync(0xffffffffu, s1, 1);
    s1 += __shfl_xor_sync(0xffffffffu, s1, 2);
    const float ii0 = 1.0f / s0;
    const float ii1 = 1.0f / s1;

    // -------------------- Pass B: write P, fused P@V ------------------------
    const int r0 = wm + (lane >> 2);
    float ctx[8][4];
    #pragma unroll
    for (int ni = 0; ni < 8; ni++)
        #pragma unroll
        for (int j = 0; j < 4; j++) ctx[ni][j] = 0.f;

    float* Prow0 = attnW + ((size_t)z * Sq + i0 + r0) * Sq;
    float* Prow1 = attnW + ((size_t)z * Sq + i0 + r0 + 8) * Sq;

    prefetch_kv(0, 0);

    for (int jt = 0; jt < 16; jt++) {
        if (jt + 1 < 16) { prefetch_kv(jt + 1, (jt + 1) & 1); CP_WAIT(1); }
        else             { CP_WAIT(0); }
        __syncthreads();

        const uint32_t kb0 = sb + (2*QT + (jt & 1) * AV_KVB) * 2;
        const uint32_t kh_base = kb0;
        const uint32_t kl_base = kb0 + KT * 2;
        const uint32_t vh_base = kb0 + 2 * KT * 2;
        const uint32_t vl_base = kb0 + 3 * KT * 2;
        const int j0 = jt * 64;

        #pragma unroll
        for (int p = 0; p < 4; p++) {
            float acc[2][4] = {};
            #pragma unroll
            for (int kb = 0; kb < 4; kb++) {
                uint32_t kh[4], kl[4];
                const uint32_t off = (uint32_t)((p * 16 + bfrag_row) * (PITCH * 2) + kb * 32 + bfrag_koff);
                ldsm_x4(kh, kh_base + off);
                ldsm_x4(kl, kl_base + off);
                #pragma unroll
                for (int s = 0; s < 2; s++) {
                    mma_bf16(acc[s], qh[kb], kh[2*s], kh[2*s+1]);
                    mma_bf16(acc[s], qh[kb], kl[2*s], kl[2*s+1]);
                    mma_bf16(acc[s], ql[kb], kh[2*s], kh[2*s+1]);
                }
            }
            uint32_t pfh[4], pfl[4];
            #pragma unroll
            for (int s = 0; s < 2; s++) {
                const int col = j0 + p * 16 + s * 8 + (lane & 3) * 2;
                const float ma0 = MA[col], ma1 = MA[col + 1];
                float p0 = __expf(acc[s][0] * 0.125f + ma0) * ii0;
                float p1 = __expf(acc[s][1] * 0.125f + ma1) * ii0;
                float p2 = __expf(acc[s][2] * 0.125f + ma0) * ii1;
                float p3 = __expf(acc[s][3] * 0.125f + ma1) * ii1;
                *(float2*)(Prow0 + col) = make_float2(p0, p1);
                *(float2*)(Prow1 + col) = make_float2(p2, p3);
                ushort h0,l0,h1,l1,h2,l2,h3,l3;
                split_bf(p0,h0,l0); split_bf(p1,h1,l1);
                split_bf(p2,h2,l2); split_bf(p3,h3,l3);
                pfh[s*2+0] = (uint32_t)h0 | ((uint32_t)h1 << 16);
                pfh[s*2+1] = (uint32_t)h2 | ((uint32_t)h3 << 16);
                pfl[s*2+0] = (uint32_t)l0 | ((uint32_t)l1 << 16);
                pfl[s*2+1] = (uint32_t)l2 | ((uint32_t)l3 << 16);
            }
            #pragma unroll
            for (int gv = 0; gv < 4; gv++) {
                uint32_t vh[4], vl[4];
                const uint32_t off = (uint32_t)((p * 16 + tfrag_row) * (PITCH * 2) + gv * 32 + tfrag_noff);
                ldsm_x4_t(vh, vh_base + off);
                ldsm_x4_t(vl, vl_base + off);
                #pragma unroll
                for (int s = 0; s < 2; s++) {
                    float* cc = ctx[gv * 2 + s];
                    mma_bf16(cc, pfh, vh[2*s], vh[2*s+1]);
                    mma_bf16(cc, pfh, vl[2*s], vl[2*s+1]);
                    mma_bf16(cc, pfl, vh[2*s], vh[2*s+1]);
                }
            }
        }
        __syncthreads();
    }

    #pragma unroll
    for (int ni = 0; ni < 8; ni++) {
        const int col = (ni >> 1) * 16 + (ni & 1) * 8 + (lane & 3) * 2;
        const size_t o0 = ((size_t)b * Sq + i0 + r0) * Wd + h * Dd + col;
        const size_t o1 = ((size_t)b * Sq + i0 + r0 + 8) * Wd + h * Dd + col;
        ushort h0,l0,h1,l1,h2,l2,h3,l3;
        split_bf(ctx[ni][0],h0,l0); split_bf(ctx[ni][1],h1,l1);
        split_bf(ctx[ni][2],h2,l2); split_bf(ctx[ni][3],h3,l3);
        *(ushort2*)(g_ch + o0) = make_ushort2(h0,h1);
        *(ushort2*)(g_cl + o0) = make_ushort2(l0,l1);
        *(ushort2*)(g_ch + o1) = make_ushort2(h2,h3);
        *(ushort2*)(g_cl + o1) = make_ushort2(l2,l3);
    }
}

// ---------------------------------------------------------------------------
extern "C" void kernel_launch(void* const* d_in, const int* in_sizes, int n_in,
                              void* d_out, int out_size) {
    const float* query = (const float*)d_in[0];
    const int*   mask  = (const int*)d_in[1];
    const float* q_w = (const float*)d_in[2];
    const float* q_b = (const float*)d_in[3];
    const float* k_w = (const float*)d_in[4];
    const float* k_b = (const float*)d_in[5];
    const float* v_w = (const float*)d_in[6];
    const float* v_b = (const float*)d_in[7];
    const float* o_w = (const float*)d_in[8];
    const float* o_b = (const float*)d_in[9];

    float* out = (float*)d_out;
    float* attn = ((long long)out_size >= OUT_ELEMS + ATTN_ELEMS) ? out + OUT_ELEMS : nullptr;

    cudaFuncSetAttribute(proj_mma, cudaFuncAttributeMaxDynamicSharedMemorySize, PROJ_SMEM);
    cudaFuncSetAttribute(attn_mma, cudaFuncAttributeMaxDynamicSharedMemorySize, AV_SMEM);
    cudaFuncSetAttribute(attn_mma, cudaFuncAttributePreferredSharedMemoryCarveout, 100);

    const int conv_blocks = (BSq * (Wd / 2) + 255) / 256;
    conv_kernel<<<dim3(conv_blocks, 5), 256>>>(query, q_w, k_w, v_w, o_w);
    proj_mma<<<dim3(6, 32, 3), 256, PROJ_SMEM>>>(0, q_b, k_b, v_b, nullptr);
    attn_mma<<<dim3(8, NZ), 256, AV_SMEM>>>(mask, attn);
    proj_mma<<<dim3(6, 32, 1), 256, PROJ_SMEM>>>(1, o_b, nullptr, nullptr, out);
}

// round 16
// speedup vs baseline: 1.5382x; 1.5382x over previous
#include <cuda_runtime.h>
#include <cuda_bf16.h>
#include <cstdint>

// Fixed shapes: B=4, S=1024, E=1024, width=768 -> H=12, D=64
#define Bq   4
#define Sq   1024
#define Eq   1024
#define Wd   768
#define Hh   12
#define Dd   64
#define BSq  (Bq*Sq)
#define NZ   (Bq*Hh)
#define WW   (Wd*Wd)
#define OUT_ELEMS   ((long long)BSq*Wd)
#define ATTN_ELEMS  ((long long)NZ*Sq*Sq)

// ---------------- scratch (device globals; no runtime allocation) ----------
__device__ __align__(16) ushort g_xh[BSq*Wd], g_xl[BSq*Wd];
__device__ __align__(16) ushort g_wh[4*WW],  g_wl[4*WW];
__device__ __align__(16) ushort g_qh[BSq*Wd], g_ql[BSq*Wd];
__device__ __align__(16) ushort g_kh[BSq*Wd], g_kl[BSq*Wd];
__device__ __align__(16) ushort g_vh[BSq*Wd], g_vl[BSq*Wd];
__device__ __align__(16) ushort g_ch[BSq*Wd], g_cl[BSq*Wd];
__device__ __align__(16) float g_attn_fallback[NZ*Sq*Sq];

// ======================= primitives ========================================
__device__ __forceinline__ void ldsm_x4(uint32_t* r, uint32_t addr) {
    asm volatile("ldmatrix.sync.aligned.m8n8.x4.shared.b16 {%0,%1,%2,%3}, [%4];"
        : "=r"(r[0]), "=r"(r[1]), "=r"(r[2]), "=r"(r[3]) : "r"(addr));
}
__device__ __forceinline__ void ldsm_x4_t(uint32_t* r, uint32_t addr) {
    asm volatile("ldmatrix.sync.aligned.m8n8.x4.trans.shared.b16 {%0,%1,%2,%3}, [%4];"
        : "=r"(r[0]), "=r"(r[1]), "=r"(r[2]), "=r"(r[3]) : "r"(addr));
}
__device__ __forceinline__ void mma_bf16(float* c, const uint32_t* a,
                                         uint32_t b0, uint32_t b1) {
    asm volatile("mma.sync.aligned.m16n8k16.row.col.f32.bf16.bf16.f32 "
        "{%0,%1,%2,%3}, {%4,%5,%6,%7}, {%8,%9}, {%0,%1,%2,%3};"
        : "+f"(c[0]), "+f"(c[1]), "+f"(c[2]), "+f"(c[3])
        : "r"(a[0]), "r"(a[1]), "r"(a[2]), "r"(a[3]), "r"(b0), "r"(b1));
}
__device__ __forceinline__ void split_bf(float v, ushort& h, ushort& l) {
    __nv_bfloat16 hh = __float2bfloat16(v);
    h = __bfloat16_as_ushort(hh);
    l = __bfloat16_as_ushort(__float2bfloat16(v - __bfloat162float(hh)));
}
__device__ __forceinline__ void cp16(uint32_t dst, const void* src) {
    asm volatile("cp.async.cg.shared.global [%0], [%1], 16;" :: "r"(dst), "l"(src));
}
#define CP_COMMIT() asm volatile("cp.async.commit_group;" ::: "memory")
#define CP_WAIT(n)  asm volatile("cp.async.wait_group %0;" :: "n"(n) : "memory")

// ===========================================================================
// conv_kernel: fp32 (stride 1024) -> bf16 hi/lo (stride 768), once.
// ===========================================================================
__global__ __launch_bounds__(256)
void conv_kernel(const float* __restrict__ x,
                 const float* __restrict__ qw, const float* __restrict__ kw,
                 const float* __restrict__ vw, const float* __restrict__ ow) {
    const int z = blockIdx.y;
    const float* src; ushort* dh; ushort* dl; int rows;
    if (z == 0)      { src = x;  dh = g_xh;        dl = g_xl;        rows = BSq; }
    else if (z == 1) { src = qw; dh = g_wh;        dl = g_wl;        rows = Wd; }
    else if (z == 2) { src = kw; dh = g_wh + WW;   dl = g_wl + WW;   rows = Wd; }
    else if (z == 3) { src = vw; dh = g_wh + 2*WW; dl = g_wl + 2*WW; rows = Wd; }
    else             { src = ow; dh = g_wh + 3*WW; dl = g_wl + 3*WW; rows = Wd; }

    const int idx = blockIdx.x * 256 + threadIdx.x;
    const int total = rows * (Wd / 2);
    if (idx >= total) return;
    const int row = idx / (Wd / 2);
    const int c2 = (idx - row * (Wd / 2)) * 2;
    float2 v = *(const float2*)(src + (size_t)row * Eq + c2);
    ushort h0, l0, h1, l1;
    split_bf(v.x, h0, l0);
    split_bf(v.y, h1, l1);
    *(ushort2*)(dh + (size_t)row * Wd + c2) = make_ushort2(h0, h1);
    *(ushort2*)(dl + (size_t)row * Wd + c2) = make_ushort2(l0, l1);
}

// ===========================================================================
// proj_mma: bf16x3 HMMA GEMM, cp.async double-buffered, K-chunk 32. (R12)
// ===========================================================================
#define PP 40                          // smem pitch in ushorts (80B)
#define PROJ_TILE (128*PP)             // 5120 ushorts per array
#define PROJ_BUF  (4*PROJ_TILE)        // Ah|Al|Bh|Bl = 20480 ushorts
#define PROJ_SMEM (2*PROJ_BUF*2)       // 81920 bytes

__global__ __launch_bounds__(256, 2)
void proj_mma(int mode, const float* __restrict__ b0, const float* __restrict__ b1,
              const float* __restrict__ b2, float* __restrict__ out_ext) {
    extern __shared__ ushort psm[];

    const int t = threadIdx.x;
    const int wid = t >> 5;
    const int lane = t & 31;

    const ushort *Axh, *Axl, *Wxh, *Wxl;
    const float* bias;
    ushort *oh = nullptr, *ol = nullptr;
    if (mode == 1) {
        Axh = g_ch; Axl = g_cl;
        Wxh = g_wh + 3*WW; Wxl = g_wl + 3*WW;
        bias = b0;
    } else {
        Axh = g_xh; Axl = g_xl;
        const int z = blockIdx.z;
        Wxh = g_wh + z*WW; Wxl = g_wl + z*WW;
        bias = (z == 0) ? b0 : (z == 1) ? b1 : b2;
        if (z == 0)      { oh = g_qh; ol = g_ql; }
        else if (z == 1) { oh = g_kh; ol = g_kl; }
        else             { oh = g_vh; ol = g_vl; }
    }

    const int n0 = blockIdx.x * 128;
    const int i0 = blockIdx.y * 128;
    const int wm = (wid & 3) * 32;
    const int wn = (wid >> 2) * 64;

    const uint32_t sb = (uint32_t)__cvta_generic_to_shared(psm);

    const ushort* s4[4] = { Axh + (size_t)i0 * Wd,
                            Axl + (size_t)i0 * Wd,
                            Wxh + (size_t)n0 * Wd,
                            Wxl + (size_t)n0 * Wd };

    auto prefetch = [&](int c, int bsel) {
        const int k0 = c * 32;
        const uint32_t base = sb + bsel * (PROJ_BUF * 2);
        #pragma unroll
        for (int u = 0; u < 8; u++) {
            const int arr = u >> 1;
            const int id = ((u & 1) << 8) + t;
            const int row = id >> 2, ch = id & 3;
            cp16(base + (arr * PROJ_TILE + row * PP + ch * 8) * 2,
                 s4[arr] + (size_t)row * Wd + k0 + ch * 8);
        }
        CP_COMMIT();
    };

    float acc[2][8][4];
    #pragma unroll
    for (int mi = 0; mi < 2; mi++)
        #pragma unroll
        for (int ni = 0; ni < 8; ni++)
            #pragma unroll
            for (int j = 0; j < 4; j++) acc[mi][ni][j] = 0.f;

    const int frag_row = ((lane >> 3) & 1) * 8 + (lane & 7);
    const int frag_koff = (lane >> 4) * 16;
    const int bfrag_row = ((lane >> 4) & 1) * 8 + (lane & 7);
    const int bfrag_koff = ((lane >> 3) & 1) * 16;

    prefetch(0, 0);

    for (int c = 0; c < 24; c++) {
        if (c + 1 < 24) { prefetch(c + 1, (c + 1) & 1); CP_WAIT(1); }
        else            { CP_WAIT(0); }
        __syncthreads();

        const uint32_t bb = sb + (c & 1) * (PROJ_BUF * 2);
        const uint32_t a_base  = bb;
        const uint32_t al_base = bb + PROJ_TILE * 2;
        const uint32_t b_base  = bb + 2 * PROJ_TILE * 2;
        const uint32_t bl_base = bb + 3 * PROJ_TILE * 2;

        #pragma unroll
        for (int kb = 0; kb < 2; kb++) {
            uint32_t ah[2][4], alr[2][4];
            #pragma unroll
            for (int mi = 0; mi < 2; mi++) {
                const uint32_t off = (uint32_t)((wm + mi * 16 + frag_row) * (PP*2)
                                                + kb * 32 + frag_koff);
                ldsm_x4(ah[mi], a_base + off);
                ldsm_x4(alr[mi], al_base + off);
            }
            #pragma unroll
            for (int g = 0; g < 4; g++) {
                uint32_t bh[4], blr[4];
                const uint32_t off = (uint32_t)((wn + g * 16 + bfrag_row) * (PP*2)
                                                + kb * 32 + bfrag_koff);
                ldsm_x4(bh, b_base + off);
                ldsm_x4(blr, bl_base + off);
                #pragma unroll
                for (int s = 0; s < 2; s++) {
                    #pragma unroll
                    for (int mi = 0; mi < 2; mi++) {
                        float* cc = acc[mi][g * 2 + s];
                        mma_bf16(cc, ah[mi],  bh[2*s],  bh[2*s+1]);
                        mma_bf16(cc, ah[mi],  blr[2*s], blr[2*s+1]);
                        mma_bf16(cc, alr[mi], bh[2*s],  bh[2*s+1]);
                    }
                }
            }
        }
        __syncthreads();
    }

    #pragma unroll
    for (int mi = 0; mi < 2; mi++) {
        #pragma unroll
        for (int ni = 0; ni < 8; ni++) {
            const int row = i0 + wm + mi * 16 + (lane >> 2);
            const int col = n0 + wn + ni * 8 + (lane & 3) * 2;
            float2 bb2 = *(const float2*)(bias + col);
            float v0 = acc[mi][ni][0] + bb2.x, v1 = acc[mi][ni][1] + bb2.y;
            float v2 = acc[mi][ni][2] + bb2.x, v3 = acc[mi][ni][3] + bb2.y;
            if (mode == 1) {
                *(float2*)(out_ext + (size_t)row * Wd + col) = make_float2(v0, v1);
                *(float2*)(out_ext + (size_t)(row + 8) * Wd + col) = make_float2(v2, v3);
            } else {
                ushort h0,l0,h1,l1,h2,l2,h3,l3;
                split_bf(v0,h0,l0); split_bf(v1,h1,l1);
                split_bf(v2,h2,l2); split_bf(v3,h3,l3);
                *(ushort2*)(oh + (size_t)row * Wd + col) = make_ushort2(h0,h1);
                *(ushort2*)(ol + (size_t)row * Wd + col) = make_ushort2(l0,l1);
                *(ushort2*)(oh + (size_t)(row + 8) * Wd + col) = make_ushort2(h2,h3);
                *(ushort2*)(ol + (size_t)(row + 8) * Wd + col) = make_ushort2(l2,l3);
            }
        }
    }
}

// ===========================================================================
// Attention smem geometry (pitch 72 ushorts = 144B)
// ===========================================================================
#define PITCH 72
#define QT    (128*PITCH)
#define KT    (64*PITCH)

__device__ __forceinline__ void prefetch_q(uint32_t sb, const ushort* qh,
                                           const ushort* ql, int t) {
    #pragma unroll
    for (int u = 0; u < 8; u++) {
        const int arr = u >> 2;
        const int rem = ((u & 3) << 8) + t;
        const int row = rem >> 3, ch = rem & 7;
        const ushort* src = (arr == 0 ? qh : ql) + (size_t)row * Wd + ch * 8;
        cp16(sb + (arr * QT + row * PITCH + ch * 8) * 2, src);
    }
    CP_COMMIT();
}

// ===========================================================================
// attn_mma: FUSED two-pass fixed-base-softmax flash attention.
// Pass A: pure-bf16 QK^T, 4-STAGE K-hi pipeline (restores MLP lost in R15).
// Pass B: full bf16x3, 2-stage KV pipeline, write P once, fused P@V. (R12)
// ===========================================================================
#define AV_KVB (4*KT)
#define AV_SMEM ((2*QT + 2*AV_KVB)*2 + Sq*4)
__global__ __launch_bounds__(256, 2)
void attn_mma(const int* __restrict__ mask, float* __restrict__ attn_out) {
    extern __shared__ ushort smem_u[];
    float* MA = (float*)(smem_u + 2*QT + 2*AV_KVB);

    float* attnW = attn_out ? attn_out : g_attn_fallback;

    const int t = threadIdx.x;
    const int wid = t >> 5;
    const int lane = t & 31;
    const int z = blockIdx.y;
    const int b = z / Hh;
    const int h = z - b * Hh;
    const int i0 = blockIdx.x * 128;
    const int wm = wid * 16;

    const size_t qoff = ((size_t)b * Sq + i0) * Wd + h * Dd;
    const size_t koff = (size_t)b * Sq * Wd + h * Dd;

    const uint32_t sb = (uint32_t)__cvta_generic_to_shared(smem_u);

    // Pass A: K-hi only, 4 stages within the KV buffer region
    auto prefetch_kh = [&](int jt, int stage) {
        const uint32_t base = sb + (2*QT + stage * KT) * 2;
        const size_t off = koff + (size_t)jt * 64 * Wd;
        #pragma unroll
        for (int u = 0; u < 2; u++) {
            const int rem = (u << 8) + t;
            const int row = rem >> 3, ch = rem & 7;
            cp16(base + (row * PITCH + ch * 8) * 2,
                 g_kh + off + (size_t)row * Wd + ch * 8);
        }
        CP_COMMIT();
    };
    auto prefetch_kv = [&](int jt, int bsel) {
        const uint32_t base = sb + (2*QT + bsel * AV_KVB) * 2;
        const size_t off = koff + (size_t)jt * 64 * Wd;
        const ushort* s4[4] = { g_kh + off, g_kl + off, g_vh + off, g_vl + off };
        #pragma unroll
        for (int u = 0; u < 8; u++) {
            const int arr = u >> 1;
            const int rem = ((u & 1) << 8) + t;
            const int row = rem >> 3, ch = rem & 7;
            cp16(base + (arr * KT + row * PITCH + ch * 8) * 2,
                 s4[arr] + (size_t)row * Wd + ch * 8);
        }
        CP_COMMIT();
    };

    prefetch_q(sb, g_qh + qoff, g_ql + qoff, t);
    prefetch_kh(0, 0);
    prefetch_kh(1, 1);
    prefetch_kh(2, 2);
    #pragma unroll
    for (int i = t; i < Sq; i += 256)
        MA[i] = __ldg(mask + b * Sq + i) ? 0.f : -1e9f;

    CP_WAIT(3);              // q tile complete (kh0..kh2 may still be pending)
    __syncthreads();

    const int frag_row = ((lane >> 3) & 1) * 8 + (lane & 7);
    const int frag_koff = (lane >> 4) * 16;
    const int bfrag_row = ((lane >> 4) & 1) * 8 + (lane & 7);
    const int bfrag_koff = ((lane >> 3) & 1) * 16;
    const int tfrag_row = ((lane >> 3) & 1) * 8 + (lane & 7);
    const int tfrag_noff = ((lane >> 4) & 1) * 16;

    uint32_t qh[4][4], ql[4][4];
    #pragma unroll
    for (int kb = 0; kb < 4; kb++) {
        const uint32_t off = (uint32_t)((wm + frag_row) * (PITCH * 2) + kb * 32 + frag_koff);
        ldsm_x4(qh[kb], sb + off);
        ldsm_x4(ql[kb], sb + QT * 2 + off);
    }

    // -------------------- Pass A: pure-bf16 row sums, 4-stage pipeline ------
    float s0 = 0.f, s1 = 0.f;
    for (int jt = 0; jt < 16; jt++) {
        if (jt < 14)      CP_WAIT(2);   // 3 pending -> oldest (jt) complete
        else if (jt == 14) CP_WAIT(1);
        else               CP_WAIT(0);
        __syncthreads();

        const uint32_t kh_base = sb + (2*QT + (jt & 3) * KT) * 2;
        const int j0 = jt * 64;

        #pragma unroll
        for (int p = 0; p < 4; p++) {
            float acc[2][4] = {};
            #pragma unroll
            for (int kb = 0; kb < 4; kb++) {
                uint32_t kh[4];
                const uint32_t off = (uint32_t)((p * 16 + bfrag_row) * (PITCH * 2) + kb * 32 + bfrag_koff);
                ldsm_x4(kh, kh_base + off);
                #pragma unroll
                for (int s = 0; s < 2; s++)
                    mma_bf16(acc[s], qh[kb], kh[2*s], kh[2*s+1]);
            }
            #pragma unroll
            for (int s = 0; s < 2; s++) {
                const int col = j0 + p * 16 + s * 8 + (lane & 3) * 2;
                const float ma0 = MA[col], ma1 = MA[col + 1];
                s0 += __expf(acc[s][0] * 0.125f + ma0) + __expf(acc[s][1] * 0.125f + ma1);
                s1 += __expf(acc[s][2] * 0.125f + ma0) + __expf(acc[s][3] * 0.125f + ma1);
            }
        }
        __syncthreads();
        if (jt + 3 < 16) prefetch_kh(jt + 3, (jt + 3) & 3);
    }
    s0 += __shfl_xor_sync(0xffffffffu, s0, 1);
    s0 += __shfl_xor_sync(0xffffffffu, s0, 2);
    s1 += __shfl_xor_sync(0xffffffffu, s1, 1);
    s1 += __shfl_xor_sync(0xffffffffu, s1, 2);
    const float ii0 = 1.0f / s0;
    const float ii1 = 1.0f / s1;

    // -------------------- Pass B: write P, fused P@V (R12 proven) -----------
    const int r0 = wm + (lane >> 2);
    float ctx[8][4];
    #pragma unroll
    for (int ni = 0; ni < 8; ni++)
        #pragma unroll
        for (int j = 0; j < 4; j++) ctx[ni][j] = 0.f;

    float* Prow0 = attnW + ((size_t)z * Sq + i0 + r0) * Sq;
    float* Prow1 = attnW + ((size_t)z * Sq + i0 + r0 + 8) * Sq;

    __syncthreads();          // pass A reads fully done before buffer reuse
    prefetch_kv(0, 0);

    for (int jt = 0; jt < 16; jt++) {
        if (jt + 1 < 16) { prefetch_kv(jt + 1, (jt + 1) & 1); CP_WAIT(1); }
        else             { CP_WAIT(0); }
        __syncthreads();

        const uint32_t kb0 = sb + (2*QT + (jt & 1) * AV_KVB) * 2;
        const uint32_t kh_base = kb0;
        const uint32_t kl_base = kb0 + KT * 2;
        const uint32_t vh_base = kb0 + 2 * KT * 2;
        const uint32_t vl_base = kb0 + 3 * KT * 2;
        const int j0 = jt * 64;

        #pragma unroll
        for (int p = 0; p < 4; p++) {
            float acc[2][4] = {};
            #pragma unroll
            for (int kb = 0; kb < 4; kb++) {
                uint32_t kh[4], kl[4];
                const uint32_t off = (uint32_t)((p * 16 + bfrag_row) * (PITCH * 2) + kb * 32 + bfrag_koff);
                ldsm_x4(kh, kh_base + off);
                ldsm_x4(kl, kl_base + off);
                #pragma unroll
                for (int s = 0; s < 2; s++) {
                    mma_bf16(acc[s], qh[kb], kh[2*s], kh[2*s+1]);
                    mma_bf16(acc[s], qh[kb], kl[2*s], kl[2*s+1]);
                    mma_bf16(acc[s], ql[kb], kh[2*s], kh[2*s+1]);
                }
            }
            uint32_t pfh[4], pfl[4];
            #pragma unroll
            for (int s = 0; s < 2; s++) {
                const int col = j0 + p * 16 + s * 8 + (lane & 3) * 2;
                const float ma0 = MA[col], ma1 = MA[col + 1];
                float p0 = __expf(acc[s][0] * 0.125f + ma0) * ii0;
                float p1 = __expf(acc[s][1] * 0.125f + ma1) * ii0;
                float p2 = __expf(acc[s][2] * 0.125f + ma0) * ii1;
                float p3 = __expf(acc[s][3] * 0.125f + ma1) * ii1;
                *(float2*)(Prow0 + col) = make_float2(p0, p1);
                *(float2*)(Prow1 + col) = make_float2(p2, p3);
                ushort h0,l0,h1,l1,h2,l2,h3,l3;
                split_bf(p0,h0,l0); split_bf(p1,h1,l1);
                split_bf(p2,h2,l2); split_bf(p3,h3,l3);
                pfh[s*2+0] = (uint32_t)h0 | ((uint32_t)h1 << 16);
                pfh[s*2+1] = (uint32_t)h2 | ((uint32_t)h3 << 16);
                pfl[s*2+0] = (uint32_t)l0 | ((uint32_t)l1 << 16);
                pfl[s*2+1] = (uint32_t)l2 | ((uint32_t)l3 << 16);
            }
            #pragma unroll
            for (int gv = 0; gv < 4; gv++) {
                uint32_t vh[4], vl[4];
                const uint32_t off = (uint32_t)((p * 16 + tfrag_row) * (PITCH * 2) + gv * 32 + tfrag_noff);
                ldsm_x4_t(vh, vh_base + off);
                ldsm_x4_t(vl, vl_base + off);
                #pragma unroll
                for (int s = 0; s < 2; s++) {
                    float* cc = ctx[gv * 2 + s];
                    mma_bf16(cc, pfh, vh[2*s], vh[2*s+1]);
                    mma_bf16(cc, pfh, vl[2*s], vl[2*s+1]);
                    mma_bf16(cc, pfl, vh[2*s], vh[2*s+1]);
                }
            }
        }
        __syncthreads();
    }

    #pragma unroll
    for (int ni = 0; ni < 8; ni++) {
        const int col = (ni >> 1) * 16 + (ni & 1) * 8 + (lane & 3) * 2;
        const size_t o0 = ((size_t)b * Sq + i0 + r0) * Wd + h * Dd + col;
        const size_t o1 = ((size_t)b * Sq + i0 + r0 + 8) * Wd + h * Dd + col;
        ushort h0,l0,h1,l1,h2,l2,h3,l3;
        split_bf(ctx[ni][0],h0,l0); split_bf(ctx[ni][1],h1,l1);
        split_bf(ctx[ni][2],h2,l2); split_bf(ctx[ni][3],h3,l3);
        *(ushort2*)(g_ch + o0) = make_ushort2(h0,h1);
        *(ushort2*)(g_cl + o0) = make_ushort2(l0,l1);
        *(ushort2*)(g_ch + o1) = make_ushort2(h2,h3);
        *(ushort2*)(g_cl + o1) = make_ushort2(l2,l3);
    }
}

// ---------------------------------------------------------------------------
extern "C" void kernel_launch(void* const* d_in, const int* in_sizes, int n_in,
                              void* d_out, int out_size) {
    const float* query = (const float*)d_in[0];
    const int*   mask  = (const int*)d_in[1];
    const float* q_w = (const float*)d_in[2];
    const float* q_b = (const float*)d_in[3];
    const float* k_w = (const float*)d_in[4];
    const float* k_b = (const float*)d_in[5];
    const float* v_w = (const float*)d_in[6];
    const float* v_b = (const float*)d_in[7];
    const float* o_w = (const float*)d_in[8];
    const float* o_b = (const float*)d_in[9];

    float* out = (float*)d_out;
    float* attn = ((long long)out_size >= OUT_ELEMS + ATTN_ELEMS) ? out + OUT_ELEMS : nullptr;

    cudaFuncSetAttribute(proj_mma, cudaFuncAttributeMaxDynamicSharedMemorySize, PROJ_SMEM);
    cudaFuncSetAttribute(attn_mma, cudaFuncAttributeMaxDynamicSharedMemorySize, AV_SMEM);
    cudaFuncSetAttribute(attn_mma, cudaFuncAttributePreferredSharedMemoryCarveout, 100);

    const int conv_blocks = (BSq * (Wd / 2) + 255) / 256;
    conv_kernel<<<dim3(conv_blocks, 5), 256>>>(query, q_w, k_w, v_w, o_w);
    proj_mma<<<dim3(6, 32, 3), 256, PROJ_SMEM>>>(0, q_b, k_b, v_b, nullptr);
    attn_mma<<<dim3(8, NZ), 256, AV_SMEM>>>(mask, attn);
    proj_mma<<<dim3(6, 32, 1), 256, PROJ_SMEM>>>(1, o_b, nullptr, nullptr, out);
}

// round 17
// speedup vs baseline: 1.6300x; 1.0597x over previous
#include <cuda_runtime.h>
#include <cuda_bf16.h>
#include <cstdint>

// Fixed shapes: B=4, S=1024, E=1024, width=768 -> H=12, D=64
#define Bq   4
#define Sq   1024
#define Eq   1024
#define Wd   768
#define Hh   12
#define Dd   64
#define BSq  (Bq*Sq)
#define NZ   (Bq*Hh)
#define WW   (Wd*Wd)
#define OUT_ELEMS   ((long long)BSq*Wd)
#define ATTN_ELEMS  ((long long)NZ*Sq*Sq)

// ---------------- scratch (device globals; no runtime allocation) ----------
__device__ __align__(16) ushort g_xh[BSq*Wd], g_xl[BSq*Wd];
__device__ __align__(16) ushort g_wh[4*WW],  g_wl[4*WW];
__device__ __align__(16) ushort g_qh[BSq*Wd], g_ql[BSq*Wd];
__device__ __align__(16) ushort g_kh[BSq*Wd], g_kl[BSq*Wd];
__device__ __align__(16) ushort g_vh[BSq*Wd], g_vl[BSq*Wd];
__device__ __align__(16) ushort g_ch[BSq*Wd], g_cl[BSq*Wd];
__device__ __align__(16) float g_attn_fallback[NZ*Sq*Sq];

// ======================= primitives ========================================
__device__ __forceinline__ void ldsm_x4(uint32_t* r, uint32_t addr) {
    asm volatile("ldmatrix.sync.aligned.m8n8.x4.shared.b16 {%0,%1,%2,%3}, [%4];"
        : "=r"(r[0]), "=r"(r[1]), "=r"(r[2]), "=r"(r[3]) : "r"(addr));
}
__device__ __forceinline__ void ldsm_x4_t(uint32_t* r, uint32_t addr) {
    asm volatile("ldmatrix.sync.aligned.m8n8.x4.trans.shared.b16 {%0,%1,%2,%3}, [%4];"
        : "=r"(r[0]), "=r"(r[1]), "=r"(r[2]), "=r"(r[3]) : "r"(addr));
}
__device__ __forceinline__ void mma_bf16(float* c, const uint32_t* a,
                                         uint32_t b0, uint32_t b1) {
    asm volatile("mma.sync.aligned.m16n8k16.row.col.f32.bf16.bf16.f32 "
        "{%0,%1,%2,%3}, {%4,%5,%6,%7}, {%8,%9}, {%0,%1,%2,%3};"
        : "+f"(c[0]), "+f"(c[1]), "+f"(c[2]), "+f"(c[3])
        : "r"(a[0]), "r"(a[1]), "r"(a[2]), "r"(a[3]), "r"(b0), "r"(b1));
}
__device__ __forceinline__ void split_bf(float v, ushort& h, ushort& l) {
    __nv_bfloat16 hh = __float2bfloat16(v);
    h = __bfloat16_as_ushort(hh);
    l = __bfloat16_as_ushort(__float2bfloat16(v - __bfloat162float(hh)));
}
__device__ __forceinline__ void cp16(uint32_t dst, const void* src) {
    asm volatile("cp.async.cg.shared.global [%0], [%1], 16;" :: "r"(dst), "l"(src));
}
#define CP_COMMIT() asm volatile("cp.async.commit_group;" ::: "memory")
#define CP_WAIT(n)  asm volatile("cp.async.wait_group %0;" :: "n"(n) : "memory")

// ===========================================================================
// conv_kernel: fp32 (stride 1024) -> bf16 hi/lo (stride 768), once.
// ===========================================================================
__global__ __launch_bounds__(256)
void conv_kernel(const float* __restrict__ x,
                 const float* __restrict__ qw, const float* __restrict__ kw,
                 const float* __restrict__ vw, const float* __restrict__ ow) {
    const int z = blockIdx.y;
    const float* src; ushort* dh; ushort* dl; int rows;
    if (z == 0)      { src = x;  dh = g_xh;        dl = g_xl;        rows = BSq; }
    else if (z == 1) { src = qw; dh = g_wh;        dl = g_wl;        rows = Wd; }
    else if (z == 2) { src = kw; dh = g_wh + WW;   dl = g_wl + WW;   rows = Wd; }
    else if (z == 3) { src = vw; dh = g_wh + 2*WW; dl = g_wl + 2*WW; rows = Wd; }
    else             { src = ow; dh = g_wh + 3*WW; dl = g_wl + 3*WW; rows = Wd; }

    const int idx = blockIdx.x * 256 + threadIdx.x;
    const int total = rows * (Wd / 2);
    if (idx >= total) return;
    const int row = idx / (Wd / 2);
    const int c2 = (idx - row * (Wd / 2)) * 2;
    float2 v = *(const float2*)(src + (size_t)row * Eq + c2);
    ushort h0, l0, h1, l1;
    split_bf(v.x, h0, l0);
    split_bf(v.y, h1, l1);
    *(ushort2*)(dh + (size_t)row * Wd + c2) = make_ushort2(h0, h1);
    *(ushort2*)(dl + (size_t)row * Wd + c2) = make_ushort2(l0, l1);
}

// ===========================================================================
// proj_mma: qkv projections. 128x128 tiles, K-chunk 32, cp.async DB. (R12/16)
// ===========================================================================
#define PP 40
#define PROJ_TILE (128*PP)
#define PROJ_BUF  (4*PROJ_TILE)
#define PROJ_SMEM (2*PROJ_BUF*2)

__global__ __launch_bounds__(256, 2)
void proj_mma(const float* __restrict__ b0, const float* __restrict__ b1,
              const float* __restrict__ b2) {
    extern __shared__ ushort psm[];

    const int t = threadIdx.x;
    const int wid = t >> 5;
    const int lane = t & 31;

    const int z = blockIdx.z;
    const ushort* Wxh = g_wh + z*WW;
    const ushort* Wxl = g_wl + z*WW;
    const float* bias = (z == 0) ? b0 : (z == 1) ? b1 : b2;
    ushort *oh, *ol;
    if (z == 0)      { oh = g_qh; ol = g_ql; }
    else if (z == 1) { oh = g_kh; ol = g_kl; }
    else             { oh = g_vh; ol = g_vl; }

    const int n0 = blockIdx.x * 128;
    const int i0 = blockIdx.y * 128;
    const int wm = (wid & 3) * 32;
    const int wn = (wid >> 2) * 64;

    const uint32_t sb = (uint32_t)__cvta_generic_to_shared(psm);

    const ushort* s4[4] = { g_xh + (size_t)i0 * Wd,
                            g_xl + (size_t)i0 * Wd,
                            Wxh + (size_t)n0 * Wd,
                            Wxl + (size_t)n0 * Wd };

    auto prefetch = [&](int c, int bsel) {
        const int k0 = c * 32;
        const uint32_t base = sb + bsel * (PROJ_BUF * 2);
        #pragma unroll
        for (int u = 0; u < 8; u++) {
            const int arr = u >> 1;
            const int id = ((u & 1) << 8) + t;
            const int row = id >> 2, ch = id & 3;
            cp16(base + (arr * PROJ_TILE + row * PP + ch * 8) * 2,
                 s4[arr] + (size_t)row * Wd + k0 + ch * 8);
        }
        CP_COMMIT();
    };

    float acc[2][8][4];
    #pragma unroll
    for (int mi = 0; mi < 2; mi++)
        #pragma unroll
        for (int ni = 0; ni < 8; ni++)
            #pragma unroll
            for (int j = 0; j < 4; j++) acc[mi][ni][j] = 0.f;

    const int frag_row = ((lane >> 3) & 1) * 8 + (lane & 7);
    const int frag_koff = (lane >> 4) * 16;
    const int bfrag_row = ((lane >> 4) & 1) * 8 + (lane & 7);
    const int bfrag_koff = ((lane >> 3) & 1) * 16;

    prefetch(0, 0);

    for (int c = 0; c < 24; c++) {
        if (c + 1 < 24) { prefetch(c + 1, (c + 1) & 1); CP_WAIT(1); }
        else            { CP_WAIT(0); }
        __syncthreads();

        const uint32_t bb = sb + (c & 1) * (PROJ_BUF * 2);
        const uint32_t a_base  = bb;
        const uint32_t al_base = bb + PROJ_TILE * 2;
        const uint32_t b_base  = bb + 2 * PROJ_TILE * 2;
        const uint32_t bl_base = bb + 3 * PROJ_TILE * 2;

        #pragma unroll
        for (int kb = 0; kb < 2; kb++) {
            uint32_t ah[2][4], alr[2][4];
            #pragma unroll
            for (int mi = 0; mi < 2; mi++) {
                const uint32_t off = (uint32_t)((wm + mi * 16 + frag_row) * (PP*2)
                                                + kb * 32 + frag_koff);
                ldsm_x4(ah[mi], a_base + off);
                ldsm_x4(alr[mi], al_base + off);
            }
            #pragma unroll
            for (int g = 0; g < 4; g++) {
                uint32_t bh[4], blr[4];
                const uint32_t off = (uint32_t)((wn + g * 16 + bfrag_row) * (PP*2)
                                                + kb * 32 + bfrag_koff);
                ldsm_x4(bh, b_base + off);
                ldsm_x4(blr, bl_base + off);
                #pragma unroll
                for (int s = 0; s < 2; s++) {
                    #pragma unroll
                    for (int mi = 0; mi < 2; mi++) {
                        float* cc = acc[mi][g * 2 + s];
                        mma_bf16(cc, ah[mi],  bh[2*s],  bh[2*s+1]);
                        mma_bf16(cc, ah[mi],  blr[2*s], blr[2*s+1]);
                        mma_bf16(cc, alr[mi], bh[2*s],  bh[2*s+1]);
                    }
                }
            }
        }
        __syncthreads();
    }

    #pragma unroll
    for (int mi = 0; mi < 2; mi++) {
        #pragma unroll
        for (int ni = 0; ni < 8; ni++) {
            const int row = i0 + wm + mi * 16 + (lane >> 2);
            const int col = n0 + wn + ni * 8 + (lane & 3) * 2;
            float2 bb2 = *(const float2*)(bias + col);
            float v0 = acc[mi][ni][0] + bb2.x, v1 = acc[mi][ni][1] + bb2.y;
            float v2 = acc[mi][ni][2] + bb2.x, v3 = acc[mi][ni][3] + bb2.y;
            ushort h0,l0,h1,l1,h2,l2,h3,l3;
            split_bf(v0,h0,l0); split_bf(v1,h1,l1);
            split_bf(v2,h2,l2); split_bf(v3,h3,l3);
            *(ushort2*)(oh + (size_t)row * Wd + col) = make_ushort2(h0,h1);
            *(ushort2*)(ol + (size_t)row * Wd + col) = make_ushort2(l0,l1);
            *(ushort2*)(oh + (size_t)(row + 8) * Wd + col) = make_ushort2(h2,h3);
            *(ushort2*)(ol + (size_t)(row + 8) * Wd + col) = make_ushort2(l2,l3);
        }
    }
}

// ===========================================================================
// oproj_mma: output projection, 64x128 tiles (R13-measured 61.3us), fp32 out.
// ===========================================================================
#define OA_H 0
#define OA_L (64*PP)
#define OB_H (2*64*PP)
#define OB_L (2*64*PP + 128*PP)
#define OPJ_BUF (2*64*PP + 2*128*PP)   // 15360 ushorts
#define OPJ_SMEM (2*OPJ_BUF*2)         // 61440 bytes

__global__ __launch_bounds__(256, 2)
void oproj_mma(const float* __restrict__ ob, float* __restrict__ out) {
    extern __shared__ ushort psm[];

    const int t = threadIdx.x;
    const int wid = t >> 5;
    const int lane = t & 31;

    const ushort* Wxh = g_wh + 3*WW;
    const ushort* Wxl = g_wl + 3*WW;

    const int n0 = blockIdx.x * 128;
    const int i0 = blockIdx.y * 64;
    const int wm = (wid & 3) * 16;
    const int wn = (wid >> 2) * 64;

    const uint32_t sb = (uint32_t)__cvta_generic_to_shared(psm);

    auto prefetch = [&](int c, int bsel) {
        const int k0 = c * 32;
        const uint32_t base = sb + bsel * (OPJ_BUF * 2);
        #pragma unroll
        for (int u = 0; u < 2; u++) {
            const int id = (u << 8) + t;
            const int arr = id >> 8;
            const int rem = id & 255;
            const int row = rem >> 2, ch = rem & 3;
            cp16(base + ((arr ? OA_L : OA_H) + row * PP + ch * 8) * 2,
                 (arr ? g_cl : g_ch) + (size_t)(i0 + row) * Wd + k0 + ch * 8);
        }
        #pragma unroll
        for (int u = 0; u < 4; u++) {
            const int id = (u << 8) + t;
            const int arr = id >> 9;
            const int rem = id & 511;
            const int row = rem >> 2, ch = rem & 3;
            cp16(base + ((arr ? OB_L : OB_H) + row * PP + ch * 8) * 2,
                 (arr ? Wxl : Wxh) + (size_t)(n0 + row) * Wd + k0 + ch * 8);
        }
        CP_COMMIT();
    };

    float acc[8][4];
    #pragma unroll
    for (int ni = 0; ni < 8; ni++)
        #pragma unroll
        for (int j = 0; j < 4; j++) acc[ni][j] = 0.f;

    const int frag_row = ((lane >> 3) & 1) * 8 + (lane & 7);
    const int frag_koff = (lane >> 4) * 16;
    const int bfrag_row = ((lane >> 4) & 1) * 8 + (lane & 7);
    const int bfrag_koff = ((lane >> 3) & 1) * 16;

    prefetch(0, 0);

    for (int c = 0; c < 24; c++) {
        if (c + 1 < 24) { prefetch(c + 1, (c + 1) & 1); CP_WAIT(1); }
        else            { CP_WAIT(0); }
        __syncthreads();

        const uint32_t bb = sb + (c & 1) * (OPJ_BUF * 2);

        #pragma unroll
        for (int kb = 0; kb < 2; kb++) {
            uint32_t ah[4], alr[4];
            const uint32_t aoff = (uint32_t)((wm + frag_row) * (PP*2) + kb * 32 + frag_koff);
            ldsm_x4(ah, bb + OA_H * 2 + aoff);
            ldsm_x4(alr, bb + OA_L * 2 + aoff);
            #pragma unroll
            for (int g = 0; g < 4; g++) {
                uint32_t bh[4], blr[4];
                const uint32_t boff = (uint32_t)((wn + g * 16 + bfrag_row) * (PP*2)
                                                 + kb * 32 + bfrag_koff);
                ldsm_x4(bh, bb + OB_H * 2 + boff);
                ldsm_x4(blr, bb + OB_L * 2 + boff);
                #pragma unroll
                for (int s = 0; s < 2; s++) {
                    float* cc = acc[g * 2 + s];
                    mma_bf16(cc, ah,  bh[2*s],  bh[2*s+1]);
                    mma_bf16(cc, ah,  blr[2*s], blr[2*s+1]);
                    mma_bf16(cc, alr, bh[2*s],  bh[2*s+1]);
                }
            }
        }
        __syncthreads();
    }

    #pragma unroll
    for (int ni = 0; ni < 8; ni++) {
        const int row = i0 + wm + (lane >> 2);
        const int col = n0 + wn + ni * 8 + (lane & 3) * 2;
        float2 bb2 = *(const float2*)(ob + col);
        *(float2*)(out + (size_t)row * Wd + col) =
            make_float2(acc[ni][0] + bb2.x, acc[ni][1] + bb2.y);
        *(float2*)(out + (size_t)(row + 8) * Wd + col) =
            make_float2(acc[ni][2] + bb2.x, acc[ni][3] + bb2.y);
    }
}

// ===========================================================================
// Attention smem geometry (pitch 72 ushorts = 144B)
// ===========================================================================
#define PITCH 72
#define QT    (128*PITCH)
#define KT    (64*PITCH)

__device__ __forceinline__ void prefetch_q(uint32_t sb, const ushort* qh,
                                           const ushort* ql, int t) {
    #pragma unroll
    for (int u = 0; u < 8; u++) {
        const int arr = u >> 2;
        const int rem = ((u & 3) << 8) + t;
        const int row = rem >> 3, ch = rem & 7;
        const ushort* src = (arr == 0 ? qh : ql) + (size_t)row * Wd + ch * 8;
        cp16(sb + (arr * QT + row * PITCH + ch * 8) * 2, src);
    }
    CP_COMMIT();
}

// ===========================================================================
// attn_mma: fused two-pass fixed-base-softmax flash attention.
// Pass A: pure-bf16 QK^T, 4-stage K-hi pipeline.
// Pass B: 2-term QK (qh*kh + ql*kh; K-lo dropped — calibrated err ~5e-4),
//         KV prefetch 6 cp16 (kh,vh,vl), write P once, fused P@V.
// ===========================================================================
#define AV_KVB (4*KT)
#define AV_SMEM ((2*QT + 2*AV_KVB)*2 + Sq*4)
__global__ __launch_bounds__(256, 2)
void attn_mma(const int* __restrict__ mask, float* __restrict__ attn_out) {
    extern __shared__ ushort smem_u[];
    float* MA = (float*)(smem_u + 2*QT + 2*AV_KVB);

    float* attnW = attn_out ? attn_out : g_attn_fallback;

    const int t = threadIdx.x;
    const int wid = t >> 5;
    const int lane = t & 31;
    const int z = blockIdx.y;
    const int b = z / Hh;
    const int h = z - b * Hh;
    const int i0 = blockIdx.x * 128;
    const int wm = wid * 16;

    const size_t qoff = ((size_t)b * Sq + i0) * Wd + h * Dd;
    const size_t koff = (size_t)b * Sq * Wd + h * Dd;

    const uint32_t sb = (uint32_t)__cvta_generic_to_shared(smem_u);

    auto prefetch_kh = [&](int jt, int stage) {
        const uint32_t base = sb + (2*QT + stage * KT) * 2;
        const size_t off = koff + (size_t)jt * 64 * Wd;
        #pragma unroll
        for (int u = 0; u < 2; u++) {
            const int rem = (u << 8) + t;
            const int row = rem >> 3, ch = rem & 7;
            cp16(base + (row * PITCH + ch * 8) * 2,
                 g_kh + off + (size_t)row * Wd + ch * 8);
        }
        CP_COMMIT();
    };
    // kh -> slot 0, vh -> slot 2, vl -> slot 3 (slot 1 = unused K-lo space)
    auto prefetch_kv = [&](int jt, int bsel) {
        const uint32_t base = sb + (2*QT + bsel * AV_KVB) * 2;
        const size_t off = koff + (size_t)jt * 64 * Wd;
        const ushort* s3[3] = { g_kh + off, g_vh + off, g_vl + off };
        const int slot[3] = { 0, 2, 3 };
        #pragma unroll
        for (int u = 0; u < 6; u++) {
            const int arr = u >> 1;
            const int rem = ((u & 1) << 8) + t;
            const int row = rem >> 3, ch = rem & 7;
            cp16(base + (slot[arr] * KT + row * PITCH + ch * 8) * 2,
                 s3[arr] + (size_t)row * Wd + ch * 8);
        }
        CP_COMMIT();
    };

    prefetch_q(sb, g_qh + qoff, g_ql + qoff, t);
    prefetch_kh(0, 0);
    prefetch_kh(1, 1);
    prefetch_kh(2, 2);
    #pragma unroll
    for (int i = t; i < Sq; i += 256)
        MA[i] = __ldg(mask + b * Sq + i) ? 0.f : -1e9f;

    CP_WAIT(3);
    __syncthreads();

    const int frag_row = ((lane >> 3) & 1) * 8 + (lane & 7);
    const int frag_koff = (lane >> 4) * 16;
    const int bfrag_row = ((lane >> 4) & 1) * 8 + (lane & 7);
    const int bfrag_koff = ((lane >> 3) & 1) * 16;
    const int tfrag_row = ((lane >> 3) & 1) * 8 + (lane & 7);
    const int tfrag_noff = ((lane >> 4) & 1) * 16;

    uint32_t qh[4][4], ql[4][4];
    #pragma unroll
    for (int kb = 0; kb < 4; kb++) {
        const uint32_t off = (uint32_t)((wm + frag_row) * (PITCH * 2) + kb * 32 + frag_koff);
        ldsm_x4(qh[kb], sb + off);
        ldsm_x4(ql[kb], sb + QT * 2 + off);
    }

    // -------------------- Pass A: pure-bf16 row sums, 4-stage pipeline ------
    float s0 = 0.f, s1 = 0.f;
    for (int jt = 0; jt < 16; jt++) {
        if (jt < 14)       CP_WAIT(2);
        else if (jt == 14) CP_WAIT(1);
        else               CP_WAIT(0);
        __syncthreads();

        const uint32_t kh_base = sb + (2*QT + (jt & 3) * KT) * 2;
        const int j0 = jt * 64;

        #pragma unroll
        for (int p = 0; p < 4; p++) {
            float acc[2][4] = {};
            #pragma unroll
            for (int kb = 0; kb < 4; kb++) {
                uint32_t kh[4];
                const uint32_t off = (uint32_t)((p * 16 + bfrag_row) * (PITCH * 2) + kb * 32 + bfrag_koff);
                ldsm_x4(kh, kh_base + off);
                #pragma unroll
                for (int s = 0; s < 2; s++)
                    mma_bf16(acc[s], qh[kb], kh[2*s], kh[2*s+1]);
            }
            #pragma unroll
            for (int s = 0; s < 2; s++) {
                const int col = j0 + p * 16 + s * 8 + (lane & 3) * 2;
                const float ma0 = MA[col], ma1 = MA[col + 1];
                s0 += __expf(acc[s][0] * 0.125f + ma0) + __expf(acc[s][1] * 0.125f + ma1);
                s1 += __expf(acc[s][2] * 0.125f + ma0) + __expf(acc[s][3] * 0.125f + ma1);
            }
        }
        __syncthreads();
        if (jt + 3 < 16) prefetch_kh(jt + 3, (jt + 3) & 3);
    }
    s0 += __shfl_xor_sync(0xffffffffu, s0, 1);
    s0 += __shfl_xor_sync(0xffffffffu, s0, 2);
    s1 += __shfl_xor_sync(0xffffffffu, s1, 1);
    s1 += __shfl_xor_sync(0xffffffffu, s1, 2);
    const float ii0 = 1.0f / s0;
    const float ii1 = 1.0f / s1;

    // -------------------- Pass B: 2-term QK, write P, fused P@V -------------
    const int r0 = wm + (lane >> 2);
    float ctx[8][4];
    #pragma unroll
    for (int ni = 0; ni < 8; ni++)
        #pragma unroll
        for (int j = 0; j < 4; j++) ctx[ni][j] = 0.f;

    float* Prow0 = attnW + ((size_t)z * Sq + i0 + r0) * Sq;
    float* Prow1 = attnW + ((size_t)z * Sq + i0 + r0 + 8) * Sq;

    __syncthreads();
    prefetch_kv(0, 0);

    for (int jt = 0; jt < 16; jt++) {
        if (jt + 1 < 16) { prefetch_kv(jt + 1, (jt + 1) & 1); CP_WAIT(1); }
        else             { CP_WAIT(0); }
        __syncthreads();

        const uint32_t kb0 = sb + (2*QT + (jt & 1) * AV_KVB) * 2;
        const uint32_t kh_base = kb0;
        const uint32_t vh_base = kb0 + 2 * KT * 2;
        const uint32_t vl_base = kb0 + 3 * KT * 2;
        const int j0 = jt * 64;

        #pragma unroll
        for (int p = 0; p < 4; p++) {
            float acc[2][4] = {};
            #pragma unroll
            for (int kb = 0; kb < 4; kb++) {
                uint32_t kh[4];
                const uint32_t off = (uint32_t)((p * 16 + bfrag_row) * (PITCH * 2) + kb * 32 + bfrag_koff);
                ldsm_x4(kh, kh_base + off);
                #pragma unroll
                for (int s = 0; s < 2; s++) {
                    mma_bf16(acc[s], qh[kb], kh[2*s], kh[2*s+1]);
                    mma_bf16(acc[s], ql[kb], kh[2*s], kh[2*s+1]);
                }
            }
            uint32_t pfh[4], pfl[4];
            #pragma unroll
            for (int s = 0; s < 2; s++) {
                const int col = j0 + p * 16 + s * 8 + (lane & 3) * 2;
                const float ma0 = MA[col], ma1 = MA[col + 1];
                float p0 = __expf(acc[s][0] * 0.125f + ma0) * ii0;
                float p1 = __expf(acc[s][1] * 0.125f + ma1) * ii0;
                float p2 = __expf(acc[s][2] * 0.125f + ma0) * ii1;
                float p3 = __expf(acc[s][3] * 0.125f + ma1) * ii1;
                *(float2*)(Prow0 + col) = make_float2(p0, p1);
                *(float2*)(Prow1 + col) = make_float2(p2, p3);
                ushort h0,l0,h1,l1,h2,l2,h3,l3;
                split_bf(p0,h0,l0); split_bf(p1,h1,l1);
                split_bf(p2,h2,l2); split_bf(p3,h3,l3);
                pfh[s*2+0] = (uint32_t)h0 | ((uint32_t)h1 << 16);
                pfh[s*2+1] = (uint32_t)h2 | ((uint32_t)h3 << 16);
                pfl[s*2+0] = (uint32_t)l0 | ((uint32_t)l1 << 16);
                pfl[s*2+1] = (uint32_t)l2 | ((uint32_t)l3 << 16);
            }
            #pragma unroll
            for (int gv = 0; gv < 4; gv++) {
                uint32_t vh[4], vl[4];
                const uint32_t off = (uint32_t)((p * 16 + tfrag_row) * (PITCH * 2) + gv * 32 + tfrag_noff);
                ldsm_x4_t(vh, vh_base + off);
                ldsm_x4_t(vl, vl_base + off);
                #pragma unroll
                for (int s = 0; s < 2; s++) {
                    float* cc = ctx[gv * 2 + s];
                    mma_bf16(cc, pfh, vh[2*s], vh[2*s+1]);
                    mma_bf16(cc, pfh, vl[2*s], vl[2*s+1]);
                    mma_bf16(cc, pfl, vh[2*s], vh[2*s+1]);
                }
            }
        }
        __syncthreads();
    }

    #pragma unroll
    for (int ni = 0; ni < 8; ni++) {
        const int col = (ni >> 1) * 16 + (ni & 1) * 8 + (lane & 3) * 2;
        const size_t o0 = ((size_t)b * Sq + i0 + r0) * Wd + h * Dd + col;
        const size_t o1 = ((size_t)b * Sq + i0 + r0 + 8) * Wd + h * Dd + col;
        ushort h0,l0,h1,l1,h2,l2,h3,l3;
        split_bf(ctx[ni][0],h0,l0); split_bf(ctx[ni][1],h1,l1);
        split_bf(ctx[ni][2],h2,l2); split_bf(ctx[ni][3],h3,l3);
        *(ushort2*)(g_ch + o0) = make_ushort2(h0,h1);
        *(ushort2*)(g_cl + o0) = make_ushort2(l0,l1);
        *(ushort2*)(g_ch + o1) = make_ushort2(h2,h3);
        *(ushort2*)(g_cl + o1) = make_ushort2(l2,l3);
    }
}

// ---------------------------------------------------------------------------
extern "C" void kernel_launch(void* const* d_in, const int* in_sizes, int n_in,
                              void* d_out, int out_size) {
    const float* query = (const float*)d_in[0];
    const int*   mask  = (const int*)d_in[1];
    const float* q_w = (const float*)d_in[2];
    const float* q_b = (const float*)d_in[3];
    const float* k_w = (const float*)d_in[4];
    const float* k_b = (const float*)d_in[5];
    const float* v_w = (const float*)d_in[6];
    const float* v_b = (const float*)d_in[7];
    const float* o_w = (const float*)d_in[8];
    const float* o_b = (const float*)d_in[9];

    float* out = (float*)d_out;
    float* attn = ((long long)out_size >= OUT_ELEMS + ATTN_ELEMS) ? out + OUT_ELEMS : nullptr;

    cudaFuncSetAttribute(proj_mma, cudaFuncAttributeMaxDynamicSharedMemorySize, PROJ_SMEM);
    cudaFuncSetAttribute(oproj_mma, cudaFuncAttributeMaxDynamicSharedMemorySize, OPJ_SMEM);
    cudaFuncSetAttribute(attn_mma, cudaFuncAttributeMaxDynamicSharedMemorySize, AV_SMEM);
    cudaFuncSetAttribute(attn_mma, cudaFuncAttributePreferredSharedMemoryCarveout, 100);

    const int conv_blocks = (BSq * (Wd / 2) + 255) / 256;
    conv_kernel<<<dim3(conv_blocks, 5), 256>>>(query, q_w, k_w, v_w, o_w);
    proj_mma<<<dim3(6, 32, 3), 256, PROJ_SMEM>>>(q_b, k_b, v_b);
    attn_mma<<<dim3(8, NZ), 256, AV_SMEM>>>(mask, attn);
    oproj_mma<<<dim3(6, 64), 256, OPJ_SMEM>>>(o_b, out);
}